// round 1
// baseline (speedup 1.0000x reference)
#include <cuda_runtime.h>

// Problem constants
#define BSZ 2
#define NSEQ 2048
#define DIMM 256
#define HH 8
#define DHD 32
#define M_TOT (BSZ*NSEQ)          // 4096
#define KK1 512
#define NN1 1536
#define NN2 512
#define REGSTRIDE (BSZ*HH*NSEQ*DHD)   // 1048576 floats per region

// ---------------- scratch (device globals; no runtime allocation) -------------
__device__ __align__(16) float g_W1[KK1*NN1];      // packed QKV weights  (3 MB)
__device__ __align__(16) float g_W2[KK1*NN2];      // packed output weights (1 MB)
__device__ __align__(16) float g_QKV[6*REGSTRIDE]; // qr,qi,kr,ki,vr,vi head-split (24 MB)
__device__ __align__(16) float g_Mr[M_TOT*DIMM];   // merged attention out real (4 MB)
__device__ __align__(16) float g_Mi[M_TOT*DIMM];   // merged attention out imag (4 MB)

// ---------------- weight packing ---------------------------------------------
// W1 columns: [qr | qi | kr | ki | vr | vi], rows: [xr-side(256) ; xi-side(256)]
__global__ void pack_w1(const float* __restrict__ wq_r, const float* __restrict__ wq_i,
                        const float* __restrict__ wkv_r, const float* __restrict__ wkv_i) {
    int idx = blockIdx.x*blockDim.x + threadIdx.x;
    if (idx >= KK1*NN1) return;
    int k = idx / NN1, c = idx % NN1;
    int reg = c >> 8, cc = c & 255;
    bool top = (k < 256);
    int kr = k & 255;
    float v;
    switch (reg) {
        case 0: v = top ? wq_r[kr*256+cc]       : -wq_i[kr*256+cc];       break; // qr
        case 1: v = top ? wq_i[kr*256+cc]       :  wq_r[kr*256+cc];       break; // qi
        case 2: v = top ? wkv_r[kr*512+cc]      : -wkv_i[kr*512+cc];      break; // kr
        case 3: v = top ? wkv_i[kr*512+cc]      :  wkv_r[kr*512+cc];      break; // ki
        case 4: v = top ? wkv_r[kr*512+256+cc]  : -wkv_i[kr*512+256+cc];  break; // vr
        default:v = top ? wkv_i[kr*512+256+cc]  :  wkv_r[kr*512+256+cc];  break; // vi
    }
    g_W1[idx] = v;
}

// W2 columns: [out_r(256) | out_i(256)], rows: [mr-side(256) ; mi-side(256)]
__global__ void pack_w2(const float* __restrict__ wo_r, const float* __restrict__ wo_i) {
    int idx = blockIdx.x*blockDim.x + threadIdx.x;
    if (idx >= KK1*NN2) return;
    int k = idx / NN2, c = idx % NN2;
    bool top = (k < 256);
    int kr = k & 255;
    int co = c & 255;
    float v;
    if (c < 256) v = top ? wo_r[kr*256+co] : -wo_i[kr*256+co];
    else         v = top ? wo_i[kr*256+co] :  wo_r[kr*256+co];
    g_W2[idx] = v;
}

// ---------------- GEMM 1: X[4096,512] @ W1[512,1536] -> head-split QKV --------
__global__ void gemm_qkv(const float* __restrict__ xr, const float* __restrict__ xi) {
    __shared__ __align__(16) float As[16][64];
    __shared__ __align__(16) float Bs[16][64];
    int tid = threadIdx.x;
    int tx = tid & 15, ty = tid >> 4;
    int mBase = blockIdx.y * 64;
    int nBase = blockIdx.x * 64;
    float acc[4][4] = {};
    for (int kt = 0; kt < KK1; kt += 16) {
        {
            int lin = tid * 4;
            int ar = lin >> 4, ak = lin & 15;
            int gm = mBase + ar, gk = kt + ak;
            const float* src = (gk < 256) ? (xr + (size_t)gm*256 + gk)
                                          : (xi + (size_t)gm*256 + gk - 256);
            float4 v = *(const float4*)src;
            As[ak+0][ar] = v.x; As[ak+1][ar] = v.y; As[ak+2][ar] = v.z; As[ak+3][ar] = v.w;
        }
        {
            int lin = tid * 4;
            int bk = lin >> 6, bc = lin & 63;
            *(float4*)&Bs[bk][bc] = *(const float4*)&g_W1[(size_t)(kt+bk)*NN1 + nBase + bc];
        }
        __syncthreads();
        #pragma unroll
        for (int k = 0; k < 16; k++) {
            float a[4], bb[4];
            #pragma unroll
            for (int i = 0; i < 4; i++) a[i] = As[k][ty*4+i];
            #pragma unroll
            for (int j = 0; j < 4; j++) bb[j] = Bs[k][tx*4+j];
            #pragma unroll
            for (int i = 0; i < 4; i++)
                #pragma unroll
                for (int j = 0; j < 4; j++) acc[i][j] += a[i]*bb[j];
        }
        __syncthreads();
    }
    #pragma unroll
    for (int i = 0; i < 4; i++) {
        int m = mBase + ty*4 + i;
        int b = m >> 11, n = m & 2047;
        #pragma unroll
        for (int j = 0; j < 4; j++) {
            int c = nBase + tx*4 + j;
            int reg = c >> 8, rem = c & 255;
            int h = rem >> 5, d = rem & 31;
            g_QKV[((size_t)(reg*BSZ*HH) + (size_t)(b*HH + h))*NSEQ*DHD + (size_t)n*DHD + d] = acc[i][j];
        }
    }
}

// ---------------- fused 4-replica flash attention ----------------------------
struct AtSmem {
    float qr[32][36];
    float qi[32][36];
    float kr[64][36];
    float ki[64][36];
    float vr[64][36];
    float vi[64][36];
    float p[4][32][72];
};

__global__ void attn_kernel() {
    extern __shared__ unsigned char smraw[];
    AtSmem& S = *reinterpret_cast<AtSmem*>(smraw);
    const int bh = blockIdx.x;                 // 0..15
    const int b = bh >> 3, h = bh & 7;
    const int row0 = blockIdx.y * 32;          // 64 row-tiles
    const int tid = threadIdx.x;               // 256 threads
    const int r = tid >> 3;                    // row within tile 0..31
    const int g = tid & 7;                     // col/dim group 0..7

    const size_t base = ((size_t)(b*HH + h)) * NSEQ * DHD;
    const float* Qr = g_QKV + 0*(size_t)REGSTRIDE + base;
    const float* Qi = g_QKV + 1*(size_t)REGSTRIDE + base;
    const float* Kr = g_QKV + 2*(size_t)REGSTRIDE + base;
    const float* Ki = g_QKV + 3*(size_t)REGSTRIDE + base;
    const float* Vr = g_QKV + 4*(size_t)REGSTRIDE + base;
    const float* Vi = g_QKV + 5*(size_t)REGSTRIDE + base;

    for (int i = tid; i < 32*32; i += 256) {
        int rr = i >> 5, dd = i & 31;
        S.qr[rr][dd] = Qr[(size_t)(row0+rr)*32 + dd];
        S.qi[rr][dd] = Qi[(size_t)(row0+rr)*32 + dd];
    }

    float m_run[4] = {-1e30f, -1e30f, -1e30f, -1e30f};
    float l_run[4] = {0.f, 0.f, 0.f, 0.f};
    float accr[4][4] = {};
    float acci[4][4] = {};
    const float scale = 0.17677669529663687f;   // 1/sqrt(32)

    for (int ct = 0; ct < NSEQ; ct += 64) {
        __syncthreads();
        for (int i = tid; i < 64*32; i += 256) {
            int rr = i >> 5, dd = i & 31;
            size_t gr = (size_t)(ct+rr)*32 + dd;
            S.kr[rr][dd] = Kr[gr];
            S.ki[rr][dd] = Ki[gr];
            S.vr[rr][dd] = Vr[gr];
            S.vi[rr][dd] = Vi[gr];
        }
        __syncthreads();

        // scores: 4 replicas x 8 columns per thread (cols j = g + 8t)
        float s[4][8];
        #pragma unroll
        for (int rep = 0; rep < 4; rep++)
            #pragma unroll
            for (int t = 0; t < 8; t++) s[rep][t] = 0.f;

        #pragma unroll
        for (int dc = 0; dc < 8; dc++) {
            float4 aR = *(const float4*)&S.qr[r][dc*4];
            float4 aI = *(const float4*)&S.qi[r][dc*4];
            #pragma unroll
            for (int t = 0; t < 8; t++) {
                int j = g + t*8;
                float4 kR = *(const float4*)&S.kr[j][dc*4];
                float4 kI = *(const float4*)&S.ki[j][dc*4];
                s[0][t] += aR.x*kR.x + aR.y*kR.y + aR.z*kR.z + aR.w*kR.w;
                s[1][t] += aR.x*kI.x + aR.y*kI.y + aR.z*kI.z + aR.w*kI.w;
                s[2][t] += aI.x*kR.x + aI.y*kR.y + aI.z*kR.z + aI.w*kR.w;
                s[3][t] += aI.x*kI.x + aI.y*kI.y + aI.z*kI.z + aI.w*kI.w;
            }
        }

        // online softmax per replica (row = 8 consecutive lanes in a warp)
        float alpha[4];
        #pragma unroll
        for (int rep = 0; rep < 4; rep++) {
            float mx = -1e30f;
            #pragma unroll
            for (int t = 0; t < 8; t++) { s[rep][t] *= scale; mx = fmaxf(mx, s[rep][t]); }
            #pragma unroll
            for (int o = 1; o < 8; o <<= 1) mx = fmaxf(mx, __shfl_xor_sync(0xffffffffu, mx, o));
            float mnew = fmaxf(m_run[rep], mx);
            alpha[rep] = __expf(m_run[rep] - mnew);
            m_run[rep] = mnew;
            float ps = 0.f;
            #pragma unroll
            for (int t = 0; t < 8; t++) {
                float p = __expf(s[rep][t] - mnew);
                S.p[rep][r][g + t*8] = p;
                ps += p;
            }
            #pragma unroll
            for (int o = 1; o < 8; o <<= 1) ps += __shfl_xor_sync(0xffffffffu, ps, o);
            l_run[rep] = l_run[rep]*alpha[rep] + ps;
        }

        #pragma unroll
        for (int rep = 0; rep < 4; rep++)
            #pragma unroll
            for (int dd = 0; dd < 4; dd++) { accr[rep][dd] *= alpha[rep]; acci[rep][dd] *= alpha[rep]; }

        __syncwarp();   // p written/read only within the row's 8 lanes (same warp)

        // A @ [vr, vi]: thread accumulates dims [4g, 4g+4) over all 64 columns
        #pragma unroll 4
        for (int j = 0; j < 64; j++) {
            float4 vR = *(const float4*)&S.vr[j][g*4];
            float4 vI = *(const float4*)&S.vi[j][g*4];
            #pragma unroll
            for (int rep = 0; rep < 4; rep++) {
                float p = S.p[rep][r][j];
                accr[rep][0] += p*vR.x; accr[rep][1] += p*vR.y;
                accr[rep][2] += p*vR.z; accr[rep][3] += p*vR.w;
                acci[rep][0] += p*vI.x; acci[rep][1] += p*vI.y;
                acci[rep][2] += p*vI.z; acci[rep][3] += p*vI.w;
            }
        }
    }

    // sign recombination:
    // o_r = A0 vr - A1 vi - A2 vi - A3 vr ;  o_i = A0 vi + A1 vr + A2 vr - A3 vi
    float n0 = 1.f/l_run[0], n1 = 1.f/l_run[1], n2 = 1.f/l_run[2], n3 = 1.f/l_run[3];
    int n = row0 + r;
    size_t midx = ((size_t)(b*NSEQ + n))*DIMM + h*DHD + g*4;
    #pragma unroll
    for (int dd = 0; dd < 4; dd++) {
        float orr = n0*accr[0][dd] - n1*acci[1][dd] - n2*acci[2][dd] - n3*accr[3][dd];
        float oii = n0*acci[0][dd] + n1*accr[1][dd] + n2*accr[2][dd] - n3*acci[3][dd];
        g_Mr[midx+dd] = orr;
        g_Mi[midx+dd] = oii;
    }
}

// ---------------- GEMM 2: [Mr|Mi][4096,512] @ W2[512,512] -> interleaved out --
__global__ void gemm_out(float* __restrict__ out) {
    __shared__ __align__(16) float As[16][64];
    __shared__ __align__(16) float Bs[16][64];
    int tid = threadIdx.x;
    int tx = tid & 15, ty = tid >> 4;
    int mBase = blockIdx.y * 64;
    int nBase = blockIdx.x * 64;
    float acc[4][4] = {};
    for (int kt = 0; kt < KK1; kt += 16) {
        {
            int lin = tid * 4;
            int ar = lin >> 4, ak = lin & 15;
            int gm = mBase + ar, gk = kt + ak;
            const float* src = (gk < 256) ? (g_Mr + (size_t)gm*256 + gk)
                                          : (g_Mi + (size_t)gm*256 + gk - 256);
            float4 v = *(const float4*)src;
            As[ak+0][ar] = v.x; As[ak+1][ar] = v.y; As[ak+2][ar] = v.z; As[ak+3][ar] = v.w;
        }
        {
            int lin = tid * 4;
            int bk = lin >> 6, bc = lin & 63;
            *(float4*)&Bs[bk][bc] = *(const float4*)&g_W2[(size_t)(kt+bk)*NN2 + nBase + bc];
        }
        __syncthreads();
        #pragma unroll
        for (int k = 0; k < 16; k++) {
            float a[4], bb[4];
            #pragma unroll
            for (int i = 0; i < 4; i++) a[i] = As[k][ty*4+i];
            #pragma unroll
            for (int j = 0; j < 4; j++) bb[j] = Bs[k][tx*4+j];
            #pragma unroll
            for (int i = 0; i < 4; i++)
                #pragma unroll
                for (int j = 0; j < 4; j++) acc[i][j] += a[i]*bb[j];
        }
        __syncthreads();
    }
    #pragma unroll
    for (int i = 0; i < 4; i++) {
        int m = mBase + ty*4 + i;
        #pragma unroll
        for (int j = 0; j < 4; j++) {
            int c = nBase + tx*4 + j;
            int dim = c & 255;
            int ri = c >> 8;           // 0 = real, 1 = imag
            out[((size_t)m*DIMM + dim)*2 + ri] = acc[i][j];
        }
    }
}

// ---------------- launch ------------------------------------------------------
extern "C" void kernel_launch(void* const* d_in, const int* in_sizes, int n_in,
                              void* d_out, int out_size) {
    const float* xr    = (const float*)d_in[0];
    const float* xi    = (const float*)d_in[1];
    const float* wq_r  = (const float*)d_in[2];
    const float* wq_i  = (const float*)d_in[3];
    const float* wkv_r = (const float*)d_in[4];
    const float* wkv_i = (const float*)d_in[5];
    const float* wo_r  = (const float*)d_in[6];
    const float* wo_i  = (const float*)d_in[7];
    float* out = (float*)d_out;

    // opt into >48KB dynamic smem (idempotent; not a stream op, capture-safe)
    cudaFuncSetAttribute(attn_kernel, cudaFuncAttributeMaxDynamicSharedMemorySize,
                         (int)sizeof(AtSmem));

    pack_w1<<<(KK1*NN1 + 255)/256, 256>>>(wq_r, wq_i, wkv_r, wkv_i);
    pack_w2<<<(KK1*NN2 + 255)/256, 256>>>(wo_r, wo_i);
    gemm_qkv<<<dim3(NN1/64, M_TOT/64), 256>>>(xr, xi);
    attn_kernel<<<dim3(BSZ*HH, NSEQ/32), 256, sizeof(AtSmem)>>>();
    gemm_out<<<dim3(NN2/64, M_TOT/64), 256>>>(out);
}

// round 2
// speedup vs baseline: 1.0000x; 1.0000x over previous
#include <cuda_runtime.h>

// Problem constants
#define BSZ 2
#define NSEQ 2048
#define DIMM 256
#define HH 8
#define DHD 32
#define M_TOT (BSZ*NSEQ)          // 4096
#define KK1 512
#define NN1 1536
#define NN2 512
#define REGSTRIDE (BSZ*HH*NSEQ*DHD)   // 1048576 floats per region

// ---------------- scratch (device globals; no runtime allocation) -------------
__device__ __align__(16) float g_W1[KK1*NN1];      // packed QKV weights  (3 MB)
__device__ __align__(16) float g_W2[KK1*NN2];      // packed output weights (1 MB)
__device__ __align__(16) float g_QKV[6*REGSTRIDE]; // qr,qi,kr,ki,vr,vi head-split (24 MB)
__device__ __align__(16) float g_Mr[M_TOT*DIMM];   // merged attention out real (4 MB)
__device__ __align__(16) float g_Mi[M_TOT*DIMM];   // merged attention out imag (4 MB)

// ---------------- weight packing ---------------------------------------------
// W1 columns: [qr | qi | kr | ki | vr | vi], rows: [xr-side(256) ; xi-side(256)]
__global__ void pack_w1(const float* __restrict__ wq_r, const float* __restrict__ wq_i,
                        const float* __restrict__ wkv_r, const float* __restrict__ wkv_i) {
    int idx = blockIdx.x*blockDim.x + threadIdx.x;
    if (idx >= KK1*NN1) return;
    int k = idx / NN1, c = idx % NN1;
    int reg = c >> 8, cc = c & 255;
    bool top = (k < 256);
    int kr = k & 255;
    float v;
    switch (reg) {
        case 0: v = top ? wq_r[kr*256+cc]       : -wq_i[kr*256+cc];       break; // qr
        case 1: v = top ? wq_i[kr*256+cc]       :  wq_r[kr*256+cc];       break; // qi
        case 2: v = top ? wkv_r[kr*512+cc]      : -wkv_i[kr*512+cc];      break; // kr
        case 3: v = top ? wkv_i[kr*512+cc]      :  wkv_r[kr*512+cc];      break; // ki
        case 4: v = top ? wkv_r[kr*512+256+cc]  : -wkv_i[kr*512+256+cc];  break; // vr
        default:v = top ? wkv_i[kr*512+256+cc]  :  wkv_r[kr*512+256+cc];  break; // vi
    }
    g_W1[idx] = v;
}

// W2 columns: [out_r(256) | out_i(256)], rows: [mr-side(256) ; mi-side(256)]
__global__ void pack_w2(const float* __restrict__ wo_r, const float* __restrict__ wo_i) {
    int idx = blockIdx.x*blockDim.x + threadIdx.x;
    if (idx >= KK1*NN2) return;
    int k = idx / NN2, c = idx % NN2;
    bool top = (k < 256);
    int kr = k & 255;
    int co = c & 255;
    float v;
    if (c < 256) v = top ? wo_r[kr*256+co] : -wo_i[kr*256+co];
    else         v = top ? wo_i[kr*256+co] :  wo_r[kr*256+co];
    g_W2[idx] = v;
}

// ---------------- GEMM 1: X[4096,512] @ W1[512,1536] -> head-split QKV --------
__global__ void gemm_qkv(const float* __restrict__ xr, const float* __restrict__ xi) {
    __shared__ __align__(16) float As[16][64];
    __shared__ __align__(16) float Bs[16][64];
    int tid = threadIdx.x;
    int tx = tid & 15, ty = tid >> 4;
    int mBase = blockIdx.y * 64;
    int nBase = blockIdx.x * 64;
    float acc[4][4] = {};
    for (int kt = 0; kt < KK1; kt += 16) {
        {
            int lin = tid * 4;
            int ar = lin >> 4, ak = lin & 15;
            int gm = mBase + ar, gk = kt + ak;
            const float* src = (gk < 256) ? (xr + (size_t)gm*256 + gk)
                                          : (xi + (size_t)gm*256 + gk - 256);
            float4 v = *(const float4*)src;
            As[ak+0][ar] = v.x; As[ak+1][ar] = v.y; As[ak+2][ar] = v.z; As[ak+3][ar] = v.w;
        }
        {
            int lin = tid * 4;
            int bk = lin >> 6, bc = lin & 63;
            *(float4*)&Bs[bk][bc] = *(const float4*)&g_W1[(size_t)(kt+bk)*NN1 + nBase + bc];
        }
        __syncthreads();
        #pragma unroll
        for (int k = 0; k < 16; k++) {
            float a[4], bb[4];
            #pragma unroll
            for (int i = 0; i < 4; i++) a[i] = As[k][ty*4+i];
            #pragma unroll
            for (int j = 0; j < 4; j++) bb[j] = Bs[k][tx*4+j];
            #pragma unroll
            for (int i = 0; i < 4; i++)
                #pragma unroll
                for (int j = 0; j < 4; j++) acc[i][j] += a[i]*bb[j];
        }
        __syncthreads();
    }
    #pragma unroll
    for (int i = 0; i < 4; i++) {
        int m = mBase + ty*4 + i;
        int b = m >> 11, n = m & 2047;
        #pragma unroll
        for (int j = 0; j < 4; j++) {
            int c = nBase + tx*4 + j;
            int reg = c >> 8, rem = c & 255;
            int h = rem >> 5, d = rem & 31;
            g_QKV[((size_t)(reg*BSZ*HH) + (size_t)(b*HH + h))*NSEQ*DHD + (size_t)n*DHD + d] = acc[i][j];
        }
    }
}

// ---------------- fused 4-replica flash attention ----------------------------
struct AtSmem {
    float qr[32][36];
    float qi[32][36];
    float kr[64][36];
    float ki[64][36];
    float vr[64][36];
    float vi[64][36];
    float p[4][32][72];
};

__global__ void attn_kernel() {
    extern __shared__ unsigned char smraw[];
    AtSmem& S = *reinterpret_cast<AtSmem*>(smraw);
    const int bh = blockIdx.x;                 // 0..15
    const int b = bh >> 3, h = bh & 7;
    const int row0 = blockIdx.y * 32;          // 64 row-tiles
    const int tid = threadIdx.x;               // 256 threads
    const int r = tid >> 3;                    // row within tile 0..31
    const int g = tid & 7;                     // col/dim group 0..7

    const size_t base = ((size_t)(b*HH + h)) * NSEQ * DHD;
    const float* Qr = g_QKV + 0*(size_t)REGSTRIDE + base;
    const float* Qi = g_QKV + 1*(size_t)REGSTRIDE + base;
    const float* Kr = g_QKV + 2*(size_t)REGSTRIDE + base;
    const float* Ki = g_QKV + 3*(size_t)REGSTRIDE + base;
    const float* Vr = g_QKV + 4*(size_t)REGSTRIDE + base;
    const float* Vi = g_QKV + 5*(size_t)REGSTRIDE + base;

    for (int i = tid; i < 32*32; i += 256) {
        int rr = i >> 5, dd = i & 31;
        S.qr[rr][dd] = Qr[(size_t)(row0+rr)*32 + dd];
        S.qi[rr][dd] = Qi[(size_t)(row0+rr)*32 + dd];
    }

    float m_run[4] = {-1e30f, -1e30f, -1e30f, -1e30f};
    float l_run[4] = {0.f, 0.f, 0.f, 0.f};
    float accr[4][4] = {};
    float acci[4][4] = {};
    const float scale = 0.17677669529663687f;   // 1/sqrt(32)

    for (int ct = 0; ct < NSEQ; ct += 64) {
        __syncthreads();
        for (int i = tid; i < 64*32; i += 256) {
            int rr = i >> 5, dd = i & 31;
            size_t gr = (size_t)(ct+rr)*32 + dd;
            S.kr[rr][dd] = Kr[gr];
            S.ki[rr][dd] = Ki[gr];
            S.vr[rr][dd] = Vr[gr];
            S.vi[rr][dd] = Vi[gr];
        }
        __syncthreads();

        // scores: 4 replicas x 8 columns per thread (cols j = g + 8t)
        float s[4][8];
        #pragma unroll
        for (int rep = 0; rep < 4; rep++)
            #pragma unroll
            for (int t = 0; t < 8; t++) s[rep][t] = 0.f;

        #pragma unroll
        for (int dc = 0; dc < 8; dc++) {
            float4 aR = *(const float4*)&S.qr[r][dc*4];
            float4 aI = *(const float4*)&S.qi[r][dc*4];
            #pragma unroll
            for (int t = 0; t < 8; t++) {
                int j = g + t*8;
                float4 kR = *(const float4*)&S.kr[j][dc*4];
                float4 kI = *(const float4*)&S.ki[j][dc*4];
                s[0][t] += aR.x*kR.x + aR.y*kR.y + aR.z*kR.z + aR.w*kR.w;
                s[1][t] += aR.x*kI.x + aR.y*kI.y + aR.z*kI.z + aR.w*kI.w;
                s[2][t] += aI.x*kR.x + aI.y*kR.y + aI.z*kR.z + aI.w*kR.w;
                s[3][t] += aI.x*kI.x + aI.y*kI.y + aI.z*kI.z + aI.w*kI.w;
            }
        }

        // online softmax per replica (row = 8 consecutive lanes in a warp)
        float alpha[4];
        #pragma unroll
        for (int rep = 0; rep < 4; rep++) {
            float mx = -1e30f;
            #pragma unroll
            for (int t = 0; t < 8; t++) { s[rep][t] *= scale; mx = fmaxf(mx, s[rep][t]); }
            #pragma unroll
            for (int o = 1; o < 8; o <<= 1) mx = fmaxf(mx, __shfl_xor_sync(0xffffffffu, mx, o));
            float mnew = fmaxf(m_run[rep], mx);
            alpha[rep] = __expf(m_run[rep] - mnew);
            m_run[rep] = mnew;
            float ps = 0.f;
            #pragma unroll
            for (int t = 0; t < 8; t++) {
                float p = __expf(s[rep][t] - mnew);
                S.p[rep][r][g + t*8] = p;
                ps += p;
            }
            #pragma unroll
            for (int o = 1; o < 8; o <<= 1) ps += __shfl_xor_sync(0xffffffffu, ps, o);
            l_run[rep] = l_run[rep]*alpha[rep] + ps;
        }

        #pragma unroll
        for (int rep = 0; rep < 4; rep++)
            #pragma unroll
            for (int dd = 0; dd < 4; dd++) { accr[rep][dd] *= alpha[rep]; acci[rep][dd] *= alpha[rep]; }

        __syncwarp();   // p written/read only within the row's 8 lanes (same warp)

        // A @ [vr, vi]: thread accumulates dims [4g, 4g+4) over all 64 columns
        #pragma unroll 4
        for (int j = 0; j < 64; j++) {
            float4 vR = *(const float4*)&S.vr[j][g*4];
            float4 vI = *(const float4*)&S.vi[j][g*4];
            #pragma unroll
            for (int rep = 0; rep < 4; rep++) {
                float p = S.p[rep][r][j];
                accr[rep][0] += p*vR.x; accr[rep][1] += p*vR.y;
                accr[rep][2] += p*vR.z; accr[rep][3] += p*vR.w;
                acci[rep][0] += p*vI.x; acci[rep][1] += p*vI.y;
                acci[rep][2] += p*vI.z; acci[rep][3] += p*vI.w;
            }
        }
    }

    // sign recombination:
    // o_r = A0 vr - A1 vi - A2 vi - A3 vr ;  o_i = A0 vi + A1 vr + A2 vr - A3 vi
    float n0 = 1.f/l_run[0], n1 = 1.f/l_run[1], n2 = 1.f/l_run[2], n3 = 1.f/l_run[3];
    int n = row0 + r;
    size_t midx = ((size_t)(b*NSEQ + n))*DIMM + h*DHD + g*4;
    #pragma unroll
    for (int dd = 0; dd < 4; dd++) {
        float orr = n0*accr[0][dd] - n1*acci[1][dd] - n2*acci[2][dd] - n3*accr[3][dd];
        float oii = n0*acci[0][dd] + n1*accr[1][dd] + n2*accr[2][dd] - n3*acci[3][dd];
        g_Mr[midx+dd] = orr;
        g_Mi[midx+dd] = oii;
    }
}

// ---------------- GEMM 2: [Mr|Mi][4096,512] @ W2[512,512] -> interleaved out --
__global__ void gemm_out(float* __restrict__ out) {
    __shared__ __align__(16) float As[16][64];
    __shared__ __align__(16) float Bs[16][64];
    int tid = threadIdx.x;
    int tx = tid & 15, ty = tid >> 4;
    int mBase = blockIdx.y * 64;
    int nBase = blockIdx.x * 64;
    float acc[4][4] = {};
    for (int kt = 0; kt < KK1; kt += 16) {
        {
            int lin = tid * 4;
            int ar = lin >> 4, ak = lin & 15;
            int gm = mBase + ar, gk = kt + ak;
            const float* src = (gk < 256) ? (g_Mr + (size_t)gm*256 + gk)
                                          : (g_Mi + (size_t)gm*256 + gk - 256);
            float4 v = *(const float4*)src;
            As[ak+0][ar] = v.x; As[ak+1][ar] = v.y; As[ak+2][ar] = v.z; As[ak+3][ar] = v.w;
        }
        {
            int lin = tid * 4;
            int bk = lin >> 6, bc = lin & 63;
            *(float4*)&Bs[bk][bc] = *(const float4*)&g_W2[(size_t)(kt+bk)*NN2 + nBase + bc];
        }
        __syncthreads();
        #pragma unroll
        for (int k = 0; k < 16; k++) {
            float a[4], bb[4];
            #pragma unroll
            for (int i = 0; i < 4; i++) a[i] = As[k][ty*4+i];
            #pragma unroll
            for (int j = 0; j < 4; j++) bb[j] = Bs[k][tx*4+j];
            #pragma unroll
            for (int i = 0; i < 4; i++)
                #pragma unroll
                for (int j = 0; j < 4; j++) acc[i][j] += a[i]*bb[j];
        }
        __syncthreads();
    }
    #pragma unroll
    for (int i = 0; i < 4; i++) {
        int m = mBase + ty*4 + i;
        #pragma unroll
        for (int j = 0; j < 4; j++) {
            int c = nBase + tx*4 + j;
            int dim = c & 255;
            int ri = c >> 8;           // 0 = real, 1 = imag
            out[((size_t)m*DIMM + dim)*2 + ri] = acc[i][j];
        }
    }
}

// ---------------- launch ------------------------------------------------------
extern "C" void kernel_launch(void* const* d_in, const int* in_sizes, int n_in,
                              void* d_out, int out_size) {
    const float* xr    = (const float*)d_in[0];
    const float* xi    = (const float*)d_in[1];
    const float* wq_r  = (const float*)d_in[2];
    const float* wq_i  = (const float*)d_in[3];
    const float* wkv_r = (const float*)d_in[4];
    const float* wkv_i = (const float*)d_in[5];
    const float* wo_r  = (const float*)d_in[6];
    const float* wo_i  = (const float*)d_in[7];
    float* out = (float*)d_out;

    // opt into >48KB dynamic smem (idempotent; not a stream op, capture-safe)
    cudaFuncSetAttribute(attn_kernel, cudaFuncAttributeMaxDynamicSharedMemorySize,
                         (int)sizeof(AtSmem));

    pack_w1<<<(KK1*NN1 + 255)/256, 256>>>(wq_r, wq_i, wkv_r, wkv_i);
    pack_w2<<<(KK1*NN2 + 255)/256, 256>>>(wo_r, wo_i);
    gemm_qkv<<<dim3(NN1/64, M_TOT/64), 256>>>(xr, xi);
    attn_kernel<<<dim3(BSZ*HH, NSEQ/32), 256, sizeof(AtSmem)>>>();
    gemm_out<<<dim3(NN2/64, M_TOT/64), 256>>>(out);
}